// round 11
// baseline (speedup 1.0000x reference)
#include <cuda_runtime.h>
#include <cstdint>

#define N_FRAMES   16384
#define NUM_BIN    257
#define NUM_CH     8
#define PLANE_F    (NUM_BIN * NUM_CH)      // 2056 floats
#define PLANE_B    (PLANE_F * 4)           // 8224 bytes
#define FRAME_B    (2 * PLANE_B)           // 16448 bytes (one frame, contiguous)
#define STAGES     4
#define FPB        16                      // frames per block
#define GRID       (N_FRAMES / FPB)        // 1024 blocks
#define SMEM_BYTES (STAGES * FRAME_B + STAGES * 8)   // slots + mbarriers

__device__ __forceinline__ void mbar_wait(uint32_t mbar_a, uint32_t parity) {
    uint32_t done;
    asm volatile(
        "{\n\t.reg .pred p;\n\t"
        "mbarrier.try_wait.parity.shared.b64 p, [%1], %2;\n\t"
        "selp.b32 %0, 1, 0, p;\n\t}"
        : "=r"(done) : "r"(mbar_a), "r"(parity) : "memory");
    while (!done) {
        asm volatile(
            "{\n\t.reg .pred p;\n\t"
            "mbarrier.try_wait.parity.shared.b64 p, [%1], %2, 0x989680;\n\t"
            "selp.b32 %0, 1, 0, p;\n\t}"
            : "=r"(done) : "r"(mbar_a), "r"(parity) : "memory");
    }
}

__device__ __forceinline__ void issue_copy(uint32_t dst_a, const char* gsrc, uint32_t mbar_a) {
    asm volatile("mbarrier.arrive.expect_tx.shared.b64 _, [%0], %1;"
                 :: "r"(mbar_a), "r"((uint32_t)FRAME_B) : "memory");
    asm volatile("cp.async.bulk.shared::cta.global.mbarrier::complete_tx::bytes "
                 "[%0], [%1], %2, [%3];"
                 :: "r"(dst_a), "l"(gsrc), "r"((uint32_t)FRAME_B), "r"(mbar_a)
                 : "memory");
}

// one half-bin item from smem frame slot
__device__ __forceinline__ void do_item(const char* slot, const float* W, int b,
                                        unsigned frame, unsigned item,
                                        float* out, unsigned active_mask) {
    unsigned bin  = item >> 1;
    unsigned half = item & 1u;

    float4 vxr = *(const float4*)(slot + bin * 32 + half * 16);
    float4 vxi = *(const float4*)(slot + bin * 32 + half * 16 + PLANE_B);

    size_t wb = (size_t)b * 2 * PLANE_F + (size_t)bin * NUM_CH + half * 4;
    float4 wr = __ldg((const float4*)(W + wb));
    float4 wi = __ldg((const float4*)(W + wb + PLANE_F));

    float pr = vxr.x * wr.x + vxr.y * wr.y + vxr.z * wr.z + vxr.w * wr.w
             + vxi.x * wi.x + vxi.y * wi.y + vxi.z * wi.z + vxi.w * wi.w;
    float pi = vxi.x * wr.x + vxi.y * wr.y + vxi.z * wr.z + vxi.w * wr.w
             - (vxr.x * wi.x + vxr.y * wi.y + vxr.z * wi.z + vxr.w * wi.w);

    pr += __shfl_xor_sync(active_mask, pr, 1);
    pi += __shfl_xor_sync(active_mask, pi, 1);

    size_t o = (size_t)frame * (2 * NUM_BIN) + half * NUM_BIN + bin;
    __stcs(out + o, half ? pi : pr);
}

__global__ __launch_bounds__(256) void beamform_kernel(
    const float* __restrict__ x,    // [16384, 2, 257, 8]
    const float* __restrict__ W,    // [24, 2, 257, 8]
    const int* __restrict__ beam,   // [16384] (int32 payload)
    float* __restrict__ out)        // [16384, 2, 257, 1]
{
    extern __shared__ __align__(128) char sm[];
    char*    slots  = sm;
    uint32_t slot_a = (uint32_t)__cvta_generic_to_shared(sm);
    uint32_t mbar_a = slot_a + STAGES * FRAME_B;

    unsigned tid = threadIdx.x;
    unsigned f0  = blockIdx.x * FPB;

    if (tid == 0) {
        #pragma unroll
        for (int s = 0; s < STAGES; s++)
            asm volatile("mbarrier.init.shared.b64 [%0], 1;"
                         :: "r"(mbar_a + s * 8) : "memory");
    }
    __syncthreads();

    // prologue: fill pipeline
    if (tid == 0) {
        #pragma unroll
        for (int s = 0; s < STAGES; s++)
            issue_copy(slot_a + s * FRAME_B,
                       (const char*)x + (size_t)(f0 + s) * FRAME_B,
                       mbar_a + s * 8);
    }

    for (int k = 0; k < FPB; k++) {
        int s = k & (STAGES - 1);
        uint32_t parity = (unsigned)(k / STAGES) & 1u;
        mbar_wait(mbar_a + s * 8, parity);

        unsigned frame = f0 + k;
        int b = __ldg(beam + frame);
        const char* slot = slots + s * FRAME_B;

        // 514 items: tid, tid+256 (both full), tail 512+tid for tid<2
        do_item(slot, W, b, frame, tid,        out, 0xffffffffu);
        do_item(slot, W, b, frame, tid + 256u, out, 0xffffffffu);
        if (tid < 2)
            do_item(slot, W, b, frame, 512u + tid, out, 0x00000003u);

        __syncthreads();   // slot fully consumed before refill

        if (tid == 0 && (k + STAGES) < FPB)
            issue_copy(slot_a + s * FRAME_B,
                       (const char*)x + (size_t)(f0 + k + STAGES) * FRAME_B,
                       mbar_a + s * 8);
    }
}

extern "C" void kernel_launch(void* const* d_in, const int* in_sizes, int n_in,
                              void* d_out, int out_size) {
    const float* x    = (const float*)d_in[0];
    const float* W    = (const float*)d_in[1];
    const int*   beam = (const int*)d_in[2];
    float*       out  = (float*)d_out;

    cudaFuncSetAttribute(beamform_kernel,
                         cudaFuncAttributeMaxDynamicSharedMemorySize, SMEM_BYTES);
    cudaFuncSetAttribute(beamform_kernel,
                         cudaFuncAttributePreferredSharedMemoryCarveout,
                         cudaSharedmemCarveoutMaxShared);

    beamform_kernel<<<GRID, 256, SMEM_BYTES>>>(x, W, beam, out);
}

// round 12
// speedup vs baseline: 1.4532x; 1.4532x over previous
#include <cuda_runtime.h>

#define N_FRAMES 16384
#define QF       (N_FRAMES / 4)       // 4096
#define NUM_BIN  257
#define NUM_CH   8
#define TOTAL    (N_FRAMES * NUM_BIN)
#define PLANE    (NUM_BIN * NUM_CH)   // 2056 floats per (frame, re/im) plane

__device__ __forceinline__ float4 ldcs4(const float* p) {
    return __ldcs((const float4*)p);
}

// minBlocks=3 -> ~85-reg budget: full 16-load front batch stays live while
// keeping 24 warps/SM resident (middle point between R7 and R8 configs).
__global__ __launch_bounds__(256, 3) void beamform_kernel(
    const float* __restrict__ x,    // [16384, 2, 257, 8]
    const float* __restrict__ W,    // [24, 2, 257, 8]
    const int* __restrict__ beam,   // [16384] (int32 payload)
    float* __restrict__ out)        // [16384, 2, 257, 1]
{
    // Each thread: half a bin (4 ch) for frames t + k*4096, k = 0..3.
    unsigned g    = blockIdx.x * 256u + threadIdx.x;  // < TOTAL/2 exactly
    unsigned e    = g >> 1;                           // (t, bin) with t < 4096
    unsigned half = g & 1u;
    unsigned t    = e / (unsigned)NUM_BIN;
    unsigned bin  = e - t * (unsigned)NUM_BIN;

    // beam gather first: longest dependent chain (beam -> W -> FMA)
    int b0 = __ldg(beam + t);
    int b1 = __ldg(beam + t + QF);
    int b2 = __ldg(beam + t + 2 * QF);
    int b3 = __ldg(beam + t + 3 * QF);

    const size_t FSTRIDE = (size_t)QF * 2 * PLANE;    // frame-group stride in x
    size_t xb = ((size_t)t * 2 * PLANE) + (size_t)bin * NUM_CH + half * 4;

    // 16 independent streaming loads — front-batched
    float4 xr0 = ldcs4(x + xb);
    float4 xi0 = ldcs4(x + xb + PLANE);
    float4 xr1 = ldcs4(x + xb + FSTRIDE);
    float4 xi1 = ldcs4(x + xb + FSTRIDE + PLANE);
    float4 xr2 = ldcs4(x + xb + 2 * FSTRIDE);
    float4 xi2 = ldcs4(x + xb + 2 * FSTRIDE + PLANE);
    float4 xr3 = ldcs4(x + xb + 3 * FSTRIDE);
    float4 xi3 = ldcs4(x + xb + 3 * FSTRIDE + PLANE);

    size_t wcol = (size_t)bin * NUM_CH + half * 4;
    size_t w0 = ((size_t)b0 * 2 * PLANE) + wcol;
    size_t w1 = ((size_t)b1 * 2 * PLANE) + wcol;
    size_t w2 = ((size_t)b2 * 2 * PLANE) + wcol;
    size_t w3 = ((size_t)b3 * 2 * PLANE) + wcol;

    float4 wr0 = __ldg((const float4*)(W + w0));
    float4 wi0 = __ldg((const float4*)(W + w0 + PLANE));
    float4 wr1 = __ldg((const float4*)(W + w1));
    float4 wi1 = __ldg((const float4*)(W + w1 + PLANE));
    float4 wr2 = __ldg((const float4*)(W + w2));
    float4 wi2 = __ldg((const float4*)(W + w2 + PLANE));
    float4 wr3 = __ldg((const float4*)(W + w3));
    float4 wi3 = __ldg((const float4*)(W + w3 + PLANE));

    float pr0 = xr0.x * wr0.x + xr0.y * wr0.y + xr0.z * wr0.z + xr0.w * wr0.w
              + xi0.x * wi0.x + xi0.y * wi0.y + xi0.z * wi0.z + xi0.w * wi0.w;
    float pi0 = xi0.x * wr0.x + xi0.y * wr0.y + xi0.z * wr0.z + xi0.w * wr0.w
              - (xr0.x * wi0.x + xr0.y * wi0.y + xr0.z * wi0.z + xr0.w * wi0.w);
    float pr1 = xr1.x * wr1.x + xr1.y * wr1.y + xr1.z * wr1.z + xr1.w * wr1.w
              + xi1.x * wi1.x + xi1.y * wi1.y + xi1.z * wi1.z + xi1.w * wi1.w;
    float pi1 = xi1.x * wr1.x + xi1.y * wr1.y + xi1.z * wr1.z + xi1.w * wr1.w
              - (xr1.x * wi1.x + xr1.y * wi1.y + xr1.z * wi1.z + xr1.w * wi1.w);
    float pr2 = xr2.x * wr2.x + xr2.y * wr2.y + xr2.z * wr2.z + xr2.w * wr2.w
              + xi2.x * wi2.x + xi2.y * wi2.y + xi2.z * wi2.z + xi2.w * wi2.w;
    float pi2 = xi2.x * wr2.x + xi2.y * wr2.y + xi2.z * wr2.z + xi2.w * wr2.w
              - (xr2.x * wi2.x + xr2.y * wi2.y + xr2.z * wi2.z + xr2.w * wi2.w);
    float pr3 = xr3.x * wr3.x + xr3.y * wr3.y + xr3.z * wr3.z + xr3.w * wr3.w
              + xi3.x * wi3.x + xi3.y * wi3.y + xi3.z * wi3.z + xi3.w * wi3.w;
    float pi3 = xi3.x * wr3.x + xi3.y * wr3.y + xi3.z * wr3.z + xi3.w * wr3.w
              - (xr3.x * wi3.x + xr3.y * wi3.y + xr3.z * wi3.z + xr3.w * wi3.w);

    // combine with partner lane (other 4 channels)
    pr0 += __shfl_xor_sync(0xffffffffu, pr0, 1);
    pi0 += __shfl_xor_sync(0xffffffffu, pi0, 1);
    pr1 += __shfl_xor_sync(0xffffffffu, pr1, 1);
    pi1 += __shfl_xor_sync(0xffffffffu, pi1, 1);
    pr2 += __shfl_xor_sync(0xffffffffu, pr2, 1);
    pi2 += __shfl_xor_sync(0xffffffffu, pi2, 1);
    pr3 += __shfl_xor_sync(0xffffffffu, pr3, 1);
    pi3 += __shfl_xor_sync(0xffffffffu, pi3, 1);

    // even lane -> out_r, odd lane -> out_i
    const size_t OSTRIDE = (size_t)QF * (2 * NUM_BIN);
    size_t o = (size_t)t * (2 * NUM_BIN) + bin + half * NUM_BIN;
    __stcs(out + o,               half ? pi0 : pr0);
    __stcs(out + o + OSTRIDE,     half ? pi1 : pr1);
    __stcs(out + o + 2 * OSTRIDE, half ? pi2 : pr2);
    __stcs(out + o + 3 * OSTRIDE, half ? pi3 : pr3);
}

extern "C" void kernel_launch(void* const* d_in, const int* in_sizes, int n_in,
                              void* d_out, int out_size) {
    const float* x    = (const float*)d_in[0];
    const float* W    = (const float*)d_in[1];
    const int*   beam = (const int*)d_in[2];
    float*       out  = (float*)d_out;

    unsigned total_threads = (unsigned)(TOTAL / 2);  // 2,105,344 = 8224 * 256
    unsigned threads = 256;
    unsigned blocks = (total_threads + threads - 1) / threads;
    beamform_kernel<<<blocks, threads>>>(x, W, beam, out);
}

// round 13
// speedup vs baseline: 1.4620x; 1.0061x over previous
#include <cuda_runtime.h>

#define N_FRAMES 16384
#define QF       (N_FRAMES / 4)       // 4096
#define NUM_BIN  257
#define NUM_CH   8
#define TOTAL    (N_FRAMES * NUM_BIN)
#define PLANE    (NUM_BIN * NUM_CH)   // 2056 floats per (frame, re/im) plane

// streaming load with 256B L2 prefetch-granularity hint: coalesces adjacent
// warps' 128B requests into fewer, larger DRAM fetches on the sequential x stream
__device__ __forceinline__ float4 ldcs4_256(const float* p) {
    float4 v;
    asm volatile("ld.global.cs.L2::256B.v4.f32 {%0,%1,%2,%3}, [%4];"
                 : "=f"(v.x), "=f"(v.y), "=f"(v.z), "=f"(v.w) : "l"(p));
    return v;
}

__global__ __launch_bounds__(256, 3) void beamform_kernel(
    const float* __restrict__ x,    // [16384, 2, 257, 8]
    const float* __restrict__ W,    // [24, 2, 257, 8]
    const int* __restrict__ beam,   // [16384] (int32 payload)
    float* __restrict__ out)        // [16384, 2, 257, 1]
{
    // Each thread: half a bin (4 ch) for frames t + k*4096, k = 0..3.
    unsigned g    = blockIdx.x * 256u + threadIdx.x;  // < TOTAL/2 exactly
    unsigned e    = g >> 1;                           // (t, bin) with t < 4096
    unsigned half = g & 1u;
    unsigned t    = e / (unsigned)NUM_BIN;
    unsigned bin  = e - t * (unsigned)NUM_BIN;

    // beam gather first: longest dependent chain (beam -> W -> FMA)
    int b0 = __ldg(beam + t);
    int b1 = __ldg(beam + t + QF);
    int b2 = __ldg(beam + t + 2 * QF);
    int b3 = __ldg(beam + t + 3 * QF);

    const size_t FSTRIDE = (size_t)QF * 2 * PLANE;    // frame-group stride in x
    size_t xb = ((size_t)t * 2 * PLANE) + (size_t)bin * NUM_CH + half * 4;

    // 16 independent streaming loads — front-batched, 256B L2 granularity
    float4 xr0 = ldcs4_256(x + xb);
    float4 xi0 = ldcs4_256(x + xb + PLANE);
    float4 xr1 = ldcs4_256(x + xb + FSTRIDE);
    float4 xi1 = ldcs4_256(x + xb + FSTRIDE + PLANE);
    float4 xr2 = ldcs4_256(x + xb + 2 * FSTRIDE);
    float4 xi2 = ldcs4_256(x + xb + 2 * FSTRIDE + PLANE);
    float4 xr3 = ldcs4_256(x + xb + 3 * FSTRIDE);
    float4 xi3 = ldcs4_256(x + xb + 3 * FSTRIDE + PLANE);

    size_t wcol = (size_t)bin * NUM_CH + half * 4;
    size_t w0 = ((size_t)b0 * 2 * PLANE) + wcol;
    size_t w1 = ((size_t)b1 * 2 * PLANE) + wcol;
    size_t w2 = ((size_t)b2 * 2 * PLANE) + wcol;
    size_t w3 = ((size_t)b3 * 2 * PLANE) + wcol;

    float4 wr0 = __ldg((const float4*)(W + w0));
    float4 wi0 = __ldg((const float4*)(W + w0 + PLANE));
    float4 wr1 = __ldg((const float4*)(W + w1));
    float4 wi1 = __ldg((const float4*)(W + w1 + PLANE));
    float4 wr2 = __ldg((const float4*)(W + w2));
    float4 wi2 = __ldg((const float4*)(W + w2 + PLANE));
    float4 wr3 = __ldg((const float4*)(W + w3));
    float4 wi3 = __ldg((const float4*)(W + w3 + PLANE));

    float pr0 = xr0.x * wr0.x + xr0.y * wr0.y + xr0.z * wr0.z + xr0.w * wr0.w
              + xi0.x * wi0.x + xi0.y * wi0.y + xi0.z * wi0.z + xi0.w * wi0.w;
    float pi0 = xi0.x * wr0.x + xi0.y * wr0.y + xi0.z * wr0.z + xi0.w * wr0.w
              - (xr0.x * wi0.x + xr0.y * wi0.y + xr0.z * wi0.z + xr0.w * wi0.w);
    float pr1 = xr1.x * wr1.x + xr1.y * wr1.y + xr1.z * wr1.z + xr1.w * wr1.w
              + xi1.x * wi1.x + xi1.y * wi1.y + xi1.z * wi1.z + xi1.w * wi1.w;
    float pi1 = xi1.x * wr1.x + xi1.y * wr1.y + xi1.z * wr1.z + xi1.w * wr1.w
              - (xr1.x * wi1.x + xr1.y * wi1.y + xr1.z * wi1.z + xr1.w * wi1.w);
    float pr2 = xr2.x * wr2.x + xr2.y * wr2.y + xr2.z * wr2.z + xr2.w * wr2.w
              + xi2.x * wi2.x + xi2.y * wi2.y + xi2.z * wi2.z + xi2.w * wi2.w;
    float pi2 = xi2.x * wr2.x + xi2.y * wr2.y + xi2.z * wr2.z + xi2.w * wr2.w
              - (xr2.x * wi2.x + xr2.y * wi2.y + xr2.z * wi2.z + xr2.w * wi2.w);
    float pr3 = xr3.x * wr3.x + xr3.y * wr3.y + xr3.z * wr3.z + xr3.w * wr3.w
              + xi3.x * wi3.x + xi3.y * wi3.y + xi3.z * wi3.z + xi3.w * wi3.w;
    float pi3 = xi3.x * wr3.x + xi3.y * wr3.y + xi3.z * wr3.z + xi3.w * wr3.w
              - (xr3.x * wi3.x + xr3.y * wi3.y + xr3.z * wi3.z + xr3.w * wi3.w);

    // combine with partner lane (other 4 channels)
    pr0 += __shfl_xor_sync(0xffffffffu, pr0, 1);
    pi0 += __shfl_xor_sync(0xffffffffu, pi0, 1);
    pr1 += __shfl_xor_sync(0xffffffffu, pr1, 1);
    pi1 += __shfl_xor_sync(0xffffffffu, pi1, 1);
    pr2 += __shfl_xor_sync(0xffffffffu, pr2, 1);
    pi2 += __shfl_xor_sync(0xffffffffu, pi2, 1);
    pr3 += __shfl_xor_sync(0xffffffffu, pr3, 1);
    pi3 += __shfl_xor_sync(0xffffffffu, pi3, 1);

    // even lane -> out_r, odd lane -> out_i
    const size_t OSTRIDE = (size_t)QF * (2 * NUM_BIN);
    size_t o = (size_t)t * (2 * NUM_BIN) + bin + half * NUM_BIN;
    __stcs(out + o,               half ? pi0 : pr0);
    __stcs(out + o + OSTRIDE,     half ? pi1 : pr1);
    __stcs(out + o + 2 * OSTRIDE, half ? pi2 : pr2);
    __stcs(out + o + 3 * OSTRIDE, half ? pi3 : pr3);
}

extern "C" void kernel_launch(void* const* d_in, const int* in_sizes, int n_in,
                              void* d_out, int out_size) {
    const float* x    = (const float*)d_in[0];
    const float* W    = (const float*)d_in[1];
    const int*   beam = (const int*)d_in[2];
    float*       out  = (float*)d_out;

    unsigned total_threads = (unsigned)(TOTAL / 2);  // 2,105,344 = 8224 * 256
    unsigned threads = 256;
    unsigned blocks = (total_threads + threads - 1) / threads;
    beamform_kernel<<<blocks, threads>>>(x, W, beam, out);
}